// round 1
// baseline (speedup 1.0000x reference)
#include <cuda_runtime.h>
#include <math.h>
#include <stdint.h>

// Problem constants
#define BATCH 4
#define SEQ   2048
#define EMB   1024
#define HEADS 16
#define HDIM  64
#define TOK   (BATCH * SEQ)          // 8192
#define QKVF  (3 * EMB)              // 3072

// Scratch (device globals — no allocation allowed)
__device__ float g_qkv[(size_t)TOK * QKVF];   // 96 MB: [token][3E]
__device__ float g_att[(size_t)TOK * EMB];    // 32 MB: [token][E] merged heads

// ---------------------------------------------------------------------------
// GEMM  C[M,N] = A[M,K] * B[N,K]^T  (+ bias[N])        (NT, both K-major)
// BM=BN=64, BK=16, 256 threads, 4x4 microtile per thread.
// ---------------------------------------------------------------------------
template <bool BIAS>
__global__ void __launch_bounds__(256) gemm_nt_kernel(
    const float* __restrict__ A, const float* __restrict__ Bm,
    const float* __restrict__ bias, float* __restrict__ C,
    int M, int N, int K)
{
    __shared__ float As[16][65];
    __shared__ float Bs[16][65];

    const int tid = threadIdx.x;
    const int tr  = tid >> 4;      // 0..15
    const int tc  = tid & 15;      // 0..15
    const int m0  = blockIdx.y * 64;
    const int n0  = blockIdx.x * 64;

    const int ldRow = tid >> 2;        // 0..63
    const int ldK   = (tid & 3) * 4;   // 0,4,8,12

    float acc[4][4] = {};

    const float* Aptr = A + (size_t)(m0 + ldRow) * K + ldK;
    const float* Bptr = Bm + (size_t)(n0 + ldRow) * K + ldK;

    for (int k0 = 0; k0 < K; k0 += 16) {
        float4 av = *(const float4*)(Aptr + k0);
        float4 bv = *(const float4*)(Bptr + k0);
        As[ldK + 0][ldRow] = av.x; As[ldK + 1][ldRow] = av.y;
        As[ldK + 2][ldRow] = av.z; As[ldK + 3][ldRow] = av.w;
        Bs[ldK + 0][ldRow] = bv.x; Bs[ldK + 1][ldRow] = bv.y;
        Bs[ldK + 2][ldRow] = bv.z; Bs[ldK + 3][ldRow] = bv.w;
        __syncthreads();
        #pragma unroll
        for (int k = 0; k < 16; k++) {
            float a[4], b[4];
            #pragma unroll
            for (int i = 0; i < 4; i++) a[i] = As[k][tr * 4 + i];
            #pragma unroll
            for (int j = 0; j < 4; j++) b[j] = Bs[k][tc * 4 + j];
            #pragma unroll
            for (int i = 0; i < 4; i++)
                #pragma unroll
                for (int j = 0; j < 4; j++)
                    acc[i][j] = fmaf(a[i], b[j], acc[i][j]);
        }
        __syncthreads();
    }

    #pragma unroll
    for (int i = 0; i < 4; i++) {
        int m = m0 + tr * 4 + i;
        #pragma unroll
        for (int j = 0; j < 4; j++) {
            int n = n0 + tc * 4 + j;
            float v = acc[i][j];
            if (BIAS) v += bias[n];
            C[(size_t)m * N + n] = v;
        }
    }
}

// ---------------------------------------------------------------------------
// Flash attention: grid (S/64, H, B), 256 threads.
// Q tile 64xD resident; stream K/V in 64-row tiles with online softmax.
// ---------------------------------------------------------------------------
#define QLD 65   // padded leading dim for Qs/Ks/Ps

__global__ void __launch_bounds__(256) flash_attn_kernel(
    const float* __restrict__ qkv, const int* __restrict__ mask,
    float* __restrict__ attn)
{
    extern __shared__ float sm[];
    float* Qs   = sm;                    // 64 * 65
    float* Ks   = Qs + 64 * QLD;         // 64 * 65
    float* Ps   = Ks + 64 * QLD;         // 64 * 65
    float* Vs   = Ps + 64 * QLD;         // 64 * 64
    float* madd = Vs + 64 * 64;          // 64

    const int tid = threadIdx.x;
    const int tr  = tid >> 4;            // 0..15 (query-row group)
    const int tc  = tid & 15;            // 0..15
    const int qb  = blockIdx.x;          // query tile
    const int h   = blockIdx.y;
    const int b   = blockIdx.z;

    const int tok0 = b * SEQ + qb * 64;
    const size_t qbase = (size_t)tok0 * QKVF + h * HDIM;

    // Load Q tile (pre-scaled by 1/sqrt(D) = 0.125)
    for (int idx = tid; idx < 64 * 64; idx += 256) {
        int r = idx >> 6, c = idx & 63;
        Qs[r * QLD + c] = qkv[qbase + (size_t)r * QKVF + c] * 0.125f;
    }

    float m[4], l[4], o[4][4];
    #pragma unroll
    for (int i = 0; i < 4; i++) {
        m[i] = -1e30f; l[i] = 0.f;
        #pragma unroll
        for (int j = 0; j < 4; j++) o[i][j] = 0.f;
    }

    for (int kb = 0; kb < SEQ / 64; kb++) {
        const int k0 = kb * 64;
        const size_t kbase = (size_t)(b * SEQ + k0) * QKVF + h * HDIM;
        __syncthreads();   // protect Ks/Vs/Ps from previous iteration
        for (int idx = tid; idx < 64 * 64; idx += 256) {
            int r = idx >> 6, c = idx & 63;
            Ks[r * QLD + c] = qkv[kbase + (size_t)r * QKVF + EMB + c];
            Vs[r * 64  + c] = qkv[kbase + (size_t)r * QKVF + 2 * EMB + c];
        }
        if (tid < 64)
            madd[tid] = (mask[b * SEQ + k0 + tid] != 0) ? 0.f : -1e9f;
        __syncthreads();

        // S = Q K^T  (64x64), thread owns rows tr*4.., cols tc*4..
        float s[4][4] = {};
        #pragma unroll 4
        for (int d = 0; d < 64; d++) {
            float a[4], bb[4];
            #pragma unroll
            for (int i = 0; i < 4; i++) a[i]  = Qs[(tr * 4 + i) * QLD + d];
            #pragma unroll
            for (int j = 0; j < 4; j++) bb[j] = Ks[(tc * 4 + j) * QLD + d];
            #pragma unroll
            for (int i = 0; i < 4; i++)
                #pragma unroll
                for (int j = 0; j < 4; j++)
                    s[i][j] = fmaf(a[i], bb[j], s[i][j]);
        }
        #pragma unroll
        for (int i = 0; i < 4; i++)
            #pragma unroll
            for (int j = 0; j < 4; j++)
                s[i][j] += madd[tc * 4 + j];

        // online softmax over the 16-lane row group
        #pragma unroll
        for (int i = 0; i < 4; i++) {
            float rm = fmaxf(fmaxf(s[i][0], s[i][1]), fmaxf(s[i][2], s[i][3]));
            #pragma unroll
            for (int off = 1; off < 16; off <<= 1)
                rm = fmaxf(rm, __shfl_xor_sync(0xffffffffu, rm, off));
            float mn = fmaxf(m[i], rm);
            float f  = __expf(m[i] - mn);
            float rs = 0.f;
            #pragma unroll
            for (int j = 0; j < 4; j++) {
                float p = __expf(s[i][j] - mn);
                s[i][j] = p;
                rs += p;
            }
            #pragma unroll
            for (int off = 1; off < 16; off <<= 1)
                rs += __shfl_xor_sync(0xffffffffu, rs, off);
            l[i] = l[i] * f + rs;
            m[i] = mn;
            #pragma unroll
            for (int j = 0; j < 4; j++) o[i][j] *= f;
            // stash P to smem
            #pragma unroll
            for (int j = 0; j < 4; j++)
                Ps[(tr * 4 + i) * QLD + tc * 4 + j] = s[i][j];
        }
        __syncthreads();

        // O += P @ V   (thread owns rows tr*4.., d-cols tc*4..)
        #pragma unroll 4
        for (int jj = 0; jj < 64; jj++) {
            float pp[4], vv[4];
            #pragma unroll
            for (int i = 0; i < 4; i++) pp[i] = Ps[(tr * 4 + i) * QLD + jj];
            #pragma unroll
            for (int j = 0; j < 4; j++) vv[j] = Vs[jj * 64 + tc * 4 + j];
            #pragma unroll
            for (int i = 0; i < 4; i++)
                #pragma unroll
                for (int j = 0; j < 4; j++)
                    o[i][j] = fmaf(pp[i], vv[j], o[i][j]);
        }
    }

    // normalize and write [token][h*64 + d]
    #pragma unroll
    for (int i = 0; i < 4; i++) {
        float inv = 1.f / l[i];
        size_t row = (size_t)(tok0 + tr * 4 + i) * EMB + h * HDIM;
        #pragma unroll
        for (int j = 0; j < 4; j++)
            attn[row + tc * 4 + j] = o[i][j] * inv;
    }
}

// ---------------------------------------------------------------------------
extern "C" void kernel_launch(void* const* d_in, const int* in_sizes, int n_in,
                              void* d_out, int out_size)
{
    const float* x     = (const float*)d_in[0];   // [4,2048,1024]
    const float* w_qkv = (const float*)d_in[1];   // [3072,1024]
    const float* w_out = (const float*)d_in[2];   // [1024,1024]
    const float* b_out = (const float*)d_in[3];   // [1024]
    const int*   mask  = (const int*)  d_in[4];   // [4,2048]
    float* out = (float*)d_out;                   // [4,2048,1024]

    float* qkv;  cudaGetSymbolAddress((void**)&qkv,  g_qkv);
    float* attn; cudaGetSymbolAddress((void**)&attn, g_att);

    // 1) QKV projection: [8192,3072] = x[8192,1024] @ w_qkv^T
    {
        dim3 grid(QKVF / 64, TOK / 64);
        gemm_nt_kernel<false><<<grid, 256>>>(x, w_qkv, nullptr, qkv,
                                             TOK, QKVF, EMB);
    }

    // 2) Flash attention per (b,h)
    {
        const int smem = (3 * 64 * QLD + 64 * 64 + 64) * sizeof(float); // 66560
        cudaFuncSetAttribute(flash_attn_kernel,
                             cudaFuncAttributeMaxDynamicSharedMemorySize, smem);
        dim3 grid(SEQ / 64, HEADS, BATCH);
        flash_attn_kernel<<<grid, 256, smem>>>(qkv, mask, attn);
    }

    // 3) Output projection + bias
    {
        dim3 grid(EMB / 64, TOK / 64);
        gemm_nt_kernel<true><<<grid, 256>>>(attn, w_out, b_out, out,
                                            TOK, EMB, EMB);
    }
}

// round 3
// speedup vs baseline: 1.6114x; 1.6114x over previous
#include <cuda_runtime.h>
#include <cuda_bf16.h>
#include <math.h>
#include <stdint.h>

// Problem constants
#define BATCH 4
#define SEQ   2048
#define EMB   1024
#define HEADS 16
#define HDIM  64
#define TOK   (BATCH * SEQ)          // 8192
#define QKVF  (3 * EMB)              // 3072

// Scratch (device globals — no allocation allowed)
__device__ float g_qkv[(size_t)TOK * QKVF];   // 96 MB
__device__ float g_att[(size_t)TOK * EMB];    // 32 MB
__device__ __nv_bfloat16 g_xh[(size_t)TOK * EMB];
__device__ __nv_bfloat16 g_xl[(size_t)TOK * EMB];
__device__ __nv_bfloat16 g_wqkvh[(size_t)QKVF * EMB];
__device__ __nv_bfloat16 g_wqkvl[(size_t)QKVF * EMB];
__device__ __nv_bfloat16 g_wouth[(size_t)EMB * EMB];
__device__ __nv_bfloat16 g_woutl[(size_t)EMB * EMB];
__device__ __nv_bfloat16 g_atth[(size_t)TOK * EMB];
__device__ __nv_bfloat16 g_attl[(size_t)TOK * EMB];

// ---------------------------------------------------------------------------
// PTX helpers — only sm_80+ features (compute_103 baseline safe)
// ---------------------------------------------------------------------------
__device__ __forceinline__ uint32_t smem_u32(const void* p) {
    uint32_t a;
    asm("{ .reg .u64 t; cvta.to.shared.u64 t, %1; cvt.u32.u64 %0, t; }"
        : "=r"(a) : "l"(p));
    return a;
}

#define CP_ASYNC16(dst, src) \
    asm volatile("cp.async.cg.shared.global [%0], [%1], 16;" :: "r"(dst), "l"(src))
#define CP_COMMIT() asm volatile("cp.async.commit_group;")
#define CP_WAIT(n)  asm volatile("cp.async.wait_group %0;" :: "n"(n))

#define LDMATRIX_X4(r0, r1, r2, r3, addr) \
    asm volatile("ldmatrix.sync.aligned.m8n8.x4.shared.b16 {%0,%1,%2,%3}, [%4];" \
                 : "=r"(r0), "=r"(r1), "=r"(r2), "=r"(r3) : "r"(addr))

#define MMA_BF16(c0, c1, c2, c3, a0, a1, a2, a3, b0, b1) \
    asm volatile("mma.sync.aligned.m16n8k16.row.col.f32.bf16.bf16.f32 " \
                 "{%0,%1,%2,%3}, {%4,%5,%6,%7}, {%8,%9}, {%0,%1,%2,%3};" \
                 : "+f"(c0), "+f"(c1), "+f"(c2), "+f"(c3) \
                 : "r"(a0), "r"(a1), "r"(a2), "r"(a3), "r"(b0), "r"(b1))

// ---------------------------------------------------------------------------
// fp32 -> bf16 hi/lo split (vectorized by 4)
// ---------------------------------------------------------------------------
__global__ void __launch_bounds__(256) split_kernel(
    const float4* __restrict__ in, __nv_bfloat16* __restrict__ hi,
    __nv_bfloat16* __restrict__ lo, int n4)
{
    int i = blockIdx.x * blockDim.x + threadIdx.x;
    if (i >= n4) return;
    float4 v = in[i];
    float f[4] = {v.x, v.y, v.z, v.w};
    __nv_bfloat16 h[4], l[4];
    #pragma unroll
    for (int j = 0; j < 4; j++) {
        h[j] = __float2bfloat16(f[j]);
        l[j] = __float2bfloat16(f[j] - __bfloat162float(h[j]));
    }
    ((uint2*)hi)[i] = *(uint2*)h;
    ((uint2*)lo)[i] = *(uint2*)l;
}

// ---------------------------------------------------------------------------
// mma.sync GEMM:  C[M,N] = A[M,K] * B[N,K]^T (+ bias[N])
// bf16 hi/lo 3-term, fp32 accum. CTA 128x128, BK=32, 8 warps (2x4),
// warp tile 64x32, cp.async 2-stage double buffer.
// ---------------------------------------------------------------------------
#define BM 128
#define BN 128
#define BK 32
#define LDSA 40                        // padded row: 32 + 8 bf16 (80 B)
#define TILE_B (128 * LDSA * 2)        // 10240 B per tile
#define STAGE_B (4 * TILE_B)           // Ah, Al, Bh, Bl
#define OFF_AH 0
#define OFF_AL TILE_B
#define OFF_BH (2 * TILE_B)
#define OFF_BL (3 * TILE_B)
#define GM_SMEM (2 * STAGE_B)          // 81920 B

template <bool BIAS>
__global__ void __launch_bounds__(256) gemm_mma_kernel(
    const __nv_bfloat16* __restrict__ Ah, const __nv_bfloat16* __restrict__ Al,
    const __nv_bfloat16* __restrict__ Bh, const __nv_bfloat16* __restrict__ Bl,
    const float* __restrict__ bias, float* __restrict__ C,
    int M, int N, int K)
{
    extern __shared__ char sm[];
    const uint32_t smb = smem_u32(sm);
    const int tid  = threadIdx.x;
    const int wid  = tid >> 5;
    const int lane = tid & 31;
    const int m0 = blockIdx.y * BM;
    const int n0 = blockIdx.x * BN;
    const int warp_m = (wid >> 2) * 64;
    const int warp_n = (wid & 3) * 32;

    // gmem load coords: 512 x 16B chunks per tile, 2 per thread
    const int r0l = (tid + 0)   >> 2, c0l = ((tid + 0)   & 3) * 8;
    const int r1l = (tid + 256) >> 2, c1l = ((tid + 256) & 3) * 8;

    auto load_chunk = [&](int k0, int buf) {
        const uint32_t sb = smb + buf * STAGE_B;
        const char* pAh = (const char*)(Ah + (size_t)m0 * K + k0);
        const char* pAl = (const char*)(Al + (size_t)m0 * K + k0);
        const char* pBh = (const char*)(Bh + (size_t)n0 * K + k0);
        const char* pBl = (const char*)(Bl + (size_t)n0 * K + k0);
        const size_t g0 = ((size_t)r0l * K + c0l) * 2;
        const size_t g1 = ((size_t)r1l * K + c1l) * 2;
        const uint32_t s0 = (r0l * LDSA + c0l) * 2;
        const uint32_t s1 = (r1l * LDSA + c1l) * 2;
        CP_ASYNC16(sb + OFF_AH + s0, pAh + g0);
        CP_ASYNC16(sb + OFF_AH + s1, pAh + g1);
        CP_ASYNC16(sb + OFF_AL + s0, pAl + g0);
        CP_ASYNC16(sb + OFF_AL + s1, pAl + g1);
        CP_ASYNC16(sb + OFF_BH + s0, pBh + g0);
        CP_ASYNC16(sb + OFF_BH + s1, pBh + g1);
        CP_ASYNC16(sb + OFF_BL + s0, pBl + g0);
        CP_ASYNC16(sb + OFF_BL + s1, pBl + g1);
    };

    float acc[4][4][4];
    #pragma unroll
    for (int i = 0; i < 4; i++)
        #pragma unroll
        for (int j = 0; j < 4; j++)
            #pragma unroll
            for (int c = 0; c < 4; c++) acc[i][j][c] = 0.f;

    const int nch = K / BK;
    load_chunk(0, 0);
    CP_COMMIT();

    // ldmatrix lane-addressing (bf16-element offsets within a tile)
    const int a_row = lane & 15;            // + warp_m + mi*16
    const int a_kof = (lane >> 4) * 8;      // k half-select
    const int bq    = lane >> 3;
    const int b_row = (bq >> 1) * 8 + (lane & 7);   // + warp_n + pair*16
    const int b_kof = (bq & 1) * 8;

    for (int ch = 0; ch < nch; ch++) {
        if (ch + 1 < nch) {
            load_chunk((ch + 1) * BK, (ch + 1) & 1);
            CP_COMMIT();
            CP_WAIT(1);
        } else {
            CP_WAIT(0);
        }
        __syncthreads();

        const uint32_t sb = smb + (ch & 1) * STAGE_B;
        #pragma unroll
        for (int ks = 0; ks < 2; ks++) {
            const int k0 = ks * 16;
            // B fragments: 4 n-frags (8 wide) via 2 x ldmatrix.x4, hi & lo
            uint32_t bh[4][2], bl[4][2];
            #pragma unroll
            for (int p = 0; p < 2; p++) {
                uint32_t boff = ((warp_n + p * 16 + b_row) * LDSA + k0 + b_kof) * 2;
                LDMATRIX_X4(bh[2*p][0], bh[2*p][1], bh[2*p+1][0], bh[2*p+1][1],
                            sb + OFF_BH + boff);
                LDMATRIX_X4(bl[2*p][0], bl[2*p][1], bl[2*p+1][0], bl[2*p+1][1],
                            sb + OFF_BL + boff);
            }
            #pragma unroll
            for (int mi = 0; mi < 4; mi++) {
                uint32_t ah[4], al[4];
                uint32_t aoff = ((warp_m + mi * 16 + a_row) * LDSA + k0 + a_kof) * 2;
                LDMATRIX_X4(ah[0], ah[1], ah[2], ah[3], sb + OFF_AH + aoff);
                LDMATRIX_X4(al[0], al[1], al[2], al[3], sb + OFF_AL + aoff);
                #pragma unroll
                for (int nj = 0; nj < 4; nj++) {
                    MMA_BF16(acc[mi][nj][0], acc[mi][nj][1], acc[mi][nj][2], acc[mi][nj][3],
                             ah[0], ah[1], ah[2], ah[3], bh[nj][0], bh[nj][1]);
                    MMA_BF16(acc[mi][nj][0], acc[mi][nj][1], acc[mi][nj][2], acc[mi][nj][3],
                             ah[0], ah[1], ah[2], ah[3], bl[nj][0], bl[nj][1]);
                    MMA_BF16(acc[mi][nj][0], acc[mi][nj][1], acc[mi][nj][2], acc[mi][nj][3],
                             al[0], al[1], al[2], al[3], bh[nj][0], bh[nj][1]);
                }
            }
        }
        __syncthreads();
    }

    // Epilogue
    const int g = lane >> 2, t = lane & 3;
    #pragma unroll
    for (int mi = 0; mi < 4; mi++) {
        const int row = m0 + warp_m + mi * 16 + g;
        #pragma unroll
        for (int nj = 0; nj < 4; nj++) {
            const int col = n0 + warp_n + nj * 8 + t * 2;
            float b0 = 0.f, b1 = 0.f;
            if (BIAS) { b0 = bias[col]; b1 = bias[col + 1]; }
            float2 v0 = {acc[mi][nj][0] + b0, acc[mi][nj][1] + b1};
            float2 v1 = {acc[mi][nj][2] + b0, acc[mi][nj][3] + b1};
            *(float2*)(C + (size_t)row * N + col)       = v0;
            *(float2*)(C + (size_t)(row + 8) * N + col) = v1;
        }
    }
}

// ---------------------------------------------------------------------------
// Flash attention: grid (S/64, H, B), 256 threads. (SIMT, unchanged from R1)
// ---------------------------------------------------------------------------
#define QLD 65

__global__ void __launch_bounds__(256) flash_attn_kernel(
    const float* __restrict__ qkv, const int* __restrict__ mask,
    float* __restrict__ attn)
{
    extern __shared__ float smf[];
    float* Qs   = smf;
    float* Ks   = Qs + 64 * QLD;
    float* Ps   = Ks + 64 * QLD;
    float* Vs   = Ps + 64 * QLD;
    float* madd = Vs + 64 * 64;

    const int tid = threadIdx.x;
    const int tr  = tid >> 4;
    const int tc  = tid & 15;
    const int qb  = blockIdx.x;
    const int h   = blockIdx.y;
    const int b   = blockIdx.z;

    const int tok0 = b * SEQ + qb * 64;
    const size_t qbase = (size_t)tok0 * QKVF + h * HDIM;

    for (int idx = tid; idx < 64 * 64; idx += 256) {
        int r = idx >> 6, c = idx & 63;
        Qs[r * QLD + c] = qkv[qbase + (size_t)r * QKVF + c] * 0.125f;
    }

    float m[4], l[4], o[4][4];
    #pragma unroll
    for (int i = 0; i < 4; i++) {
        m[i] = -1e30f; l[i] = 0.f;
        #pragma unroll
        for (int j = 0; j < 4; j++) o[i][j] = 0.f;
    }

    for (int kb = 0; kb < SEQ / 64; kb++) {
        const int k0 = kb * 64;
        const size_t kbase = (size_t)(b * SEQ + k0) * QKVF + h * HDIM;
        __syncthreads();
        for (int idx = tid; idx < 64 * 64; idx += 256) {
            int r = idx >> 6, c = idx & 63;
            Ks[r * QLD + c] = qkv[kbase + (size_t)r * QKVF + EMB + c];
            Vs[r * 64  + c] = qkv[kbase + (size_t)r * QKVF + 2 * EMB + c];
        }
        if (tid < 64)
            madd[tid] = (mask[b * SEQ + k0 + tid] != 0) ? 0.f : -1e9f;
        __syncthreads();

        float s[4][4] = {};
        #pragma unroll 4
        for (int d = 0; d < 64; d++) {
            float a[4], bb[4];
            #pragma unroll
            for (int i = 0; i < 4; i++) a[i]  = Qs[(tr * 4 + i) * QLD + d];
            #pragma unroll
            for (int j = 0; j < 4; j++) bb[j] = Ks[(tc * 4 + j) * QLD + d];
            #pragma unroll
            for (int i = 0; i < 4; i++)
                #pragma unroll
                for (int j = 0; j < 4; j++)
                    s[i][j] = fmaf(a[i], bb[j], s[i][j]);
        }
        #pragma unroll
        for (int i = 0; i < 4; i++)
            #pragma unroll
            for (int j = 0; j < 4; j++)
                s[i][j] += madd[tc * 4 + j];

        #pragma unroll
        for (int i = 0; i < 4; i++) {
            float rm = fmaxf(fmaxf(s[i][0], s[i][1]), fmaxf(s[i][2], s[i][3]));
            #pragma unroll
            for (int off = 1; off < 16; off <<= 1)
                rm = fmaxf(rm, __shfl_xor_sync(0xffffffffu, rm, off));
            float mn = fmaxf(m[i], rm);
            float f  = __expf(m[i] - mn);
            float rs = 0.f;
            #pragma unroll
            for (int j = 0; j < 4; j++) {
                float p = __expf(s[i][j] - mn);
                s[i][j] = p;
                rs += p;
            }
            #pragma unroll
            for (int off = 1; off < 16; off <<= 1)
                rs += __shfl_xor_sync(0xffffffffu, rs, off);
            l[i] = l[i] * f + rs;
            m[i] = mn;
            #pragma unroll
            for (int j = 0; j < 4; j++) o[i][j] *= f;
            #pragma unroll
            for (int j = 0; j < 4; j++)
                Ps[(tr * 4 + i) * QLD + tc * 4 + j] = s[i][j];
        }
        __syncthreads();

        #pragma unroll 4
        for (int jj = 0; jj < 64; jj++) {
            float pp[4], vv[4];
            #pragma unroll
            for (int i = 0; i < 4; i++) pp[i] = Ps[(tr * 4 + i) * QLD + jj];
            #pragma unroll
            for (int j = 0; j < 4; j++) vv[j] = Vs[jj * 64 + tc * 4 + j];
            #pragma unroll
            for (int i = 0; i < 4; i++)
                #pragma unroll
                for (int j = 0; j < 4; j++)
                    o[i][j] = fmaf(pp[i], vv[j], o[i][j]);
        }
    }

    #pragma unroll
    for (int i = 0; i < 4; i++) {
        float inv = 1.f / l[i];
        size_t row = (size_t)(tok0 + tr * 4 + i) * EMB + h * HDIM;
        #pragma unroll
        for (int j = 0; j < 4; j++)
            attn[row + tc * 4 + j] = o[i][j] * inv;
    }
}

// ---------------------------------------------------------------------------
extern "C" void kernel_launch(void* const* d_in, const int* in_sizes, int n_in,
                              void* d_out, int out_size)
{
    const float* x     = (const float*)d_in[0];
    const float* w_qkv = (const float*)d_in[1];
    const float* w_out = (const float*)d_in[2];
    const float* b_out = (const float*)d_in[3];
    const int*   mask  = (const int*)  d_in[4];
    float* out = (float*)d_out;

    float* qkv;  cudaGetSymbolAddress((void**)&qkv,  g_qkv);
    float* attn; cudaGetSymbolAddress((void**)&attn, g_att);
    __nv_bfloat16 *xh, *xl, *wqh, *wql, *woh, *wol, *ath, *atl;
    cudaGetSymbolAddress((void**)&xh,  g_xh);
    cudaGetSymbolAddress((void**)&xl,  g_xl);
    cudaGetSymbolAddress((void**)&wqh, g_wqkvh);
    cudaGetSymbolAddress((void**)&wql, g_wqkvl);
    cudaGetSymbolAddress((void**)&woh, g_wouth);
    cudaGetSymbolAddress((void**)&wol, g_woutl);
    cudaGetSymbolAddress((void**)&ath, g_atth);
    cudaGetSymbolAddress((void**)&atl, g_attl);

    cudaFuncSetAttribute(gemm_mma_kernel<false>,
                         cudaFuncAttributeMaxDynamicSharedMemorySize, GM_SMEM);
    cudaFuncSetAttribute(gemm_mma_kernel<true>,
                         cudaFuncAttributeMaxDynamicSharedMemorySize, GM_SMEM);

    // 0) splits
    {
        int n4 = TOK * EMB / 4;
        split_kernel<<<(n4 + 255) / 256, 256>>>((const float4*)x, xh, xl, n4);
        n4 = QKVF * EMB / 4;
        split_kernel<<<(n4 + 255) / 256, 256>>>((const float4*)w_qkv, wqh, wql, n4);
        n4 = EMB * EMB / 4;
        split_kernel<<<(n4 + 255) / 256, 256>>>((const float4*)w_out, woh, wol, n4);
    }

    // 1) QKV projection (tensor cores): [8192,3072] = x @ w_qkv^T
    {
        dim3 grid(QKVF / BN, TOK / BM);
        gemm_mma_kernel<false><<<grid, 256, GM_SMEM>>>(
            xh, xl, wqh, wql, nullptr, qkv, TOK, QKVF, EMB);
    }

    // 2) Flash attention per (b,h)
    {
        const int smem = (3 * 64 * QLD + 64 * 64 + 64) * sizeof(float);
        cudaFuncSetAttribute(flash_attn_kernel,
                             cudaFuncAttributeMaxDynamicSharedMemorySize, smem);
        dim3 grid(SEQ / 64, HEADS, BATCH);
        flash_attn_kernel<<<grid, 256, smem>>>(qkv, mask, attn);
    }

    // 3) split attention output, then output projection (tensor cores)
    {
        int n4 = TOK * EMB / 4;
        split_kernel<<<(n4 + 255) / 256, 256>>>((const float4*)attn, ath, atl, n4);
        dim3 grid(EMB / BN, TOK / BM);
        gemm_mma_kernel<true><<<grid, 256, GM_SMEM>>>(
            ath, atl, woh, wol, b_out, out, TOK, EMB, EMB);
    }
}

// round 4
// speedup vs baseline: 3.6951x; 2.2932x over previous
#include <cuda_runtime.h>
#include <cuda_bf16.h>
#include <math.h>
#include <stdint.h>

// Problem constants
#define BATCH 4
#define SEQ   2048
#define EMB   1024
#define HEADS 16
#define HDIM  64
#define TOK   (BATCH * SEQ)          // 8192
#define QKVF  (3 * EMB)              // 3072

// Scratch (device globals — no allocation allowed)
__device__ __nv_bfloat16 g_xh[(size_t)TOK * EMB];
__device__ __nv_bfloat16 g_xl[(size_t)TOK * EMB];
__device__ __nv_bfloat16 g_wqkvh[(size_t)QKVF * EMB];
__device__ __nv_bfloat16 g_wqkvl[(size_t)QKVF * EMB];
__device__ __nv_bfloat16 g_wouth[(size_t)EMB * EMB];
__device__ __nv_bfloat16 g_woutl[(size_t)EMB * EMB];
__device__ __nv_bfloat16 g_qkvh[(size_t)TOK * QKVF];
__device__ __nv_bfloat16 g_qkvl[(size_t)TOK * QKVF];
__device__ __nv_bfloat16 g_atth[(size_t)TOK * EMB];
__device__ __nv_bfloat16 g_attl[(size_t)TOK * EMB];

// ---------------------------------------------------------------------------
// PTX helpers — only sm_80+ features (compute_103 baseline safe)
// ---------------------------------------------------------------------------
__device__ __forceinline__ uint32_t smem_u32(const void* p) {
    uint32_t a;
    asm("{ .reg .u64 t; cvta.to.shared.u64 t, %1; cvt.u32.u64 %0, t; }"
        : "=r"(a) : "l"(p));
    return a;
}

#define CP_ASYNC16(dst, src) \
    asm volatile("cp.async.cg.shared.global [%0], [%1], 16;" :: "r"(dst), "l"(src))
#define CP_COMMIT() asm volatile("cp.async.commit_group;")
#define CP_WAIT(n)  asm volatile("cp.async.wait_group %0;" :: "n"(n))

#define LDMATRIX_X4(r0, r1, r2, r3, addr) \
    asm volatile("ldmatrix.sync.aligned.m8n8.x4.shared.b16 {%0,%1,%2,%3}, [%4];" \
                 : "=r"(r0), "=r"(r1), "=r"(r2), "=r"(r3) : "r"(addr))
#define LDMATRIX_X4_T(r0, r1, r2, r3, addr) \
    asm volatile("ldmatrix.sync.aligned.m8n8.x4.trans.shared.b16 {%0,%1,%2,%3}, [%4];" \
                 : "=r"(r0), "=r"(r1), "=r"(r2), "=r"(r3) : "r"(addr))

#define MMA_BF16(c0, c1, c2, c3, a0, a1, a2, a3, b0, b1) \
    asm volatile("mma.sync.aligned.m16n8k16.row.col.f32.bf16.bf16.f32 " \
                 "{%0,%1,%2,%3}, {%4,%5,%6,%7}, {%8,%9}, {%0,%1,%2,%3};" \
                 : "+f"(c0), "+f"(c1), "+f"(c2), "+f"(c3) \
                 : "r"(a0), "r"(a1), "r"(a2), "r"(a3), "r"(b0), "r"(b1))

__device__ __forceinline__ float ex2f(float x) {
    float y;
    asm("ex2.approx.f32 %0, %1;" : "=f"(y) : "f"(x));
    return y;
}

// pack two floats into bf16x2 hi, return residual bf16x2 lo via out-param
__device__ __forceinline__ uint32_t pack_hi_lo(float a, float b, uint32_t& lo) {
    __nv_bfloat162 h = __floats2bfloat162_rn(a, b);
    float ra = a - __bfloat162float(h.x);
    float rb = b - __bfloat162float(h.y);
    __nv_bfloat162 r = __floats2bfloat162_rn(ra, rb);
    lo = reinterpret_cast<uint32_t&>(r);
    return reinterpret_cast<uint32_t&>(h);
}

// ---------------------------------------------------------------------------
// fp32 -> bf16 hi/lo split (vectorized by 4)
// ---------------------------------------------------------------------------
__global__ void __launch_bounds__(256) split_kernel(
    const float4* __restrict__ in, __nv_bfloat16* __restrict__ hi,
    __nv_bfloat16* __restrict__ lo, int n4)
{
    int i = blockIdx.x * blockDim.x + threadIdx.x;
    if (i >= n4) return;
    float4 v = in[i];
    float f[4] = {v.x, v.y, v.z, v.w};
    __nv_bfloat16 h[4], l[4];
    #pragma unroll
    for (int j = 0; j < 4; j++) {
        h[j] = __float2bfloat16(f[j]);
        l[j] = __float2bfloat16(f[j] - __bfloat162float(h[j]));
    }
    ((uint2*)hi)[i] = *(uint2*)h;
    ((uint2*)lo)[i] = *(uint2*)l;
}

// ---------------------------------------------------------------------------
// mma.sync GEMM:  C[M,N] = A[M,K] * B[N,K]^T (+ bias[N])
// bf16 hi/lo 3-term, fp32 accum. CTA 128x128, BK=32, 8 warps (2x4).
// SPLIT: write bf16 hi/lo outputs instead of f32.
// ---------------------------------------------------------------------------
#define BM 128
#define BN 128
#define BK 32
#define LDSA 40
#define TILE_B (128 * LDSA * 2)
#define STAGE_B (4 * TILE_B)
#define OFF_AH 0
#define OFF_AL TILE_B
#define OFF_BH (2 * TILE_B)
#define OFF_BL (3 * TILE_B)
#define GM_SMEM (2 * STAGE_B)

template <bool BIAS, bool SPLIT>
__global__ void __launch_bounds__(256) gemm_mma_kernel(
    const __nv_bfloat16* __restrict__ Ah, const __nv_bfloat16* __restrict__ Al,
    const __nv_bfloat16* __restrict__ Bh, const __nv_bfloat16* __restrict__ Bl,
    const float* __restrict__ bias, float* __restrict__ C,
    __nv_bfloat16* __restrict__ Ch, __nv_bfloat16* __restrict__ Cl,
    int M, int N, int K)
{
    extern __shared__ char sm[];
    const uint32_t smb = smem_u32(sm);
    const int tid  = threadIdx.x;
    const int wid  = tid >> 5;
    const int lane = tid & 31;
    const int m0 = blockIdx.y * BM;
    const int n0 = blockIdx.x * BN;
    const int warp_m = (wid >> 2) * 64;
    const int warp_n = (wid & 3) * 32;

    const int r0l = (tid + 0)   >> 2, c0l = ((tid + 0)   & 3) * 8;
    const int r1l = (tid + 256) >> 2, c1l = ((tid + 256) & 3) * 8;

    auto load_chunk = [&](int k0, int buf) {
        const uint32_t sb = smb + buf * STAGE_B;
        const char* pAh = (const char*)(Ah + (size_t)m0 * K + k0);
        const char* pAl = (const char*)(Al + (size_t)m0 * K + k0);
        const char* pBh = (const char*)(Bh + (size_t)n0 * K + k0);
        const char* pBl = (const char*)(Bl + (size_t)n0 * K + k0);
        const size_t g0 = ((size_t)r0l * K + c0l) * 2;
        const size_t g1 = ((size_t)r1l * K + c1l) * 2;
        const uint32_t s0 = (r0l * LDSA + c0l) * 2;
        const uint32_t s1 = (r1l * LDSA + c1l) * 2;
        CP_ASYNC16(sb + OFF_AH + s0, pAh + g0);
        CP_ASYNC16(sb + OFF_AH + s1, pAh + g1);
        CP_ASYNC16(sb + OFF_AL + s0, pAl + g0);
        CP_ASYNC16(sb + OFF_AL + s1, pAl + g1);
        CP_ASYNC16(sb + OFF_BH + s0, pBh + g0);
        CP_ASYNC16(sb + OFF_BH + s1, pBh + g1);
        CP_ASYNC16(sb + OFF_BL + s0, pBl + g0);
        CP_ASYNC16(sb + OFF_BL + s1, pBl + g1);
    };

    float acc[4][4][4];
    #pragma unroll
    for (int i = 0; i < 4; i++)
        #pragma unroll
        for (int j = 0; j < 4; j++)
            #pragma unroll
            for (int c = 0; c < 4; c++) acc[i][j][c] = 0.f;

    const int nch = K / BK;
    load_chunk(0, 0);
    CP_COMMIT();

    const int a_row = lane & 15;
    const int a_kof = (lane >> 4) * 8;
    const int bq    = lane >> 3;
    const int b_row = (bq >> 1) * 8 + (lane & 7);
    const int b_kof = (bq & 1) * 8;

    for (int ch = 0; ch < nch; ch++) {
        if (ch + 1 < nch) {
            load_chunk((ch + 1) * BK, (ch + 1) & 1);
            CP_COMMIT();
            CP_WAIT(1);
        } else {
            CP_WAIT(0);
        }
        __syncthreads();

        const uint32_t sb = smb + (ch & 1) * STAGE_B;
        #pragma unroll
        for (int ks = 0; ks < 2; ks++) {
            const int k0 = ks * 16;
            uint32_t bh[4][2], bl[4][2];
            #pragma unroll
            for (int p = 0; p < 2; p++) {
                uint32_t boff = ((warp_n + p * 16 + b_row) * LDSA + k0 + b_kof) * 2;
                LDMATRIX_X4(bh[2*p][0], bh[2*p][1], bh[2*p+1][0], bh[2*p+1][1],
                            sb + OFF_BH + boff);
                LDMATRIX_X4(bl[2*p][0], bl[2*p][1], bl[2*p+1][0], bl[2*p+1][1],
                            sb + OFF_BL + boff);
            }
            #pragma unroll
            for (int mi = 0; mi < 4; mi++) {
                uint32_t ah[4], al[4];
                uint32_t aoff = ((warp_m + mi * 16 + a_row) * LDSA + k0 + a_kof) * 2;
                LDMATRIX_X4(ah[0], ah[1], ah[2], ah[3], sb + OFF_AH + aoff);
                LDMATRIX_X4(al[0], al[1], al[2], al[3], sb + OFF_AL + aoff);
                #pragma unroll
                for (int nj = 0; nj < 4; nj++) {
                    MMA_BF16(acc[mi][nj][0], acc[mi][nj][1], acc[mi][nj][2], acc[mi][nj][3],
                             ah[0], ah[1], ah[2], ah[3], bh[nj][0], bh[nj][1]);
                    MMA_BF16(acc[mi][nj][0], acc[mi][nj][1], acc[mi][nj][2], acc[mi][nj][3],
                             ah[0], ah[1], ah[2], ah[3], bl[nj][0], bl[nj][1]);
                    MMA_BF16(acc[mi][nj][0], acc[mi][nj][1], acc[mi][nj][2], acc[mi][nj][3],
                             al[0], al[1], al[2], al[3], bh[nj][0], bh[nj][1]);
                }
            }
        }
        __syncthreads();
    }

    const int g = lane >> 2, t = lane & 3;
    #pragma unroll
    for (int mi = 0; mi < 4; mi++) {
        const int row = m0 + warp_m + mi * 16 + g;
        #pragma unroll
        for (int nj = 0; nj < 4; nj++) {
            const int col = n0 + warp_n + nj * 8 + t * 2;
            if (SPLIT) {
                uint32_t lo0, lo1;
                uint32_t hi0 = pack_hi_lo(acc[mi][nj][0], acc[mi][nj][1], lo0);
                uint32_t hi1 = pack_hi_lo(acc[mi][nj][2], acc[mi][nj][3], lo1);
                *(uint32_t*)(Ch + (size_t)row * N + col)       = hi0;
                *(uint32_t*)(Cl + (size_t)row * N + col)       = lo0;
                *(uint32_t*)(Ch + (size_t)(row + 8) * N + col) = hi1;
                *(uint32_t*)(Cl + (size_t)(row + 8) * N + col) = lo1;
            } else {
                float b0 = 0.f, b1 = 0.f;
                if (BIAS) { b0 = bias[col]; b1 = bias[col + 1]; }
                float2 v0 = {acc[mi][nj][0] + b0, acc[mi][nj][1] + b1};
                float2 v1 = {acc[mi][nj][2] + b0, acc[mi][nj][3] + b1};
                *(float2*)(C + (size_t)row * N + col)       = v0;
                *(float2*)(C + (size_t)(row + 8) * N + col) = v1;
            }
        }
    }
}

// ---------------------------------------------------------------------------
// Flash attention with mma.sync (bf16 hi/lo, fp32 softmax & accum)
// grid (SEQ/128, HEADS, BATCH), 256 threads (8 warps x 16 q-rows).
// KV streamed in 64-key chunks, cp.async double-buffered.
// ---------------------------------------------------------------------------
#define FA_LDS 72                           // bf16 elems per smem row (padded)
#define FA_ROWB (FA_LDS * 2)                // 144 bytes
#define FA_TILE (64 * FA_ROWB)              // 9216 bytes
#define FA_OFF_QH 0
#define FA_OFF_QL (128 * FA_ROWB)           // 18432
#define FA_OFF_KV (2 * 128 * FA_ROWB)       // 36864
#define FA_KH 0
#define FA_KL FA_TILE
#define FA_VH (2 * FA_TILE)
#define FA_VL (3 * FA_TILE)
#define FA_STAGE (4 * FA_TILE)              // 36864
#define FA_OFF_MADD (FA_OFF_KV + 2 * FA_STAGE)   // 110592
#define FA_SMEM (FA_OFF_MADD + 2 * 64 * 4)       // 111104
#define FA_C1 0.18033688011112042f          // 0.125 * log2(e)

__global__ void __launch_bounds__(256) flash_mma_kernel(
    const __nv_bfloat16* __restrict__ qkh, const __nv_bfloat16* __restrict__ qkl,
    const int* __restrict__ mask,
    __nv_bfloat16* __restrict__ oh, __nv_bfloat16* __restrict__ ol)
{
    extern __shared__ char sm[];
    const uint32_t smb = smem_u32(sm);
    const int tid = threadIdx.x, wid = tid >> 5, lane = tid & 31;
    const int qb = blockIdx.x, h = blockIdx.y, b = blockIdx.z;
    const int tok0 = b * SEQ + qb * 128;

    // KV + mask chunk loader
    auto load_kv = [&](int ch) {
        const uint32_t stg = smb + FA_OFF_KV + (ch & 1) * FA_STAGE;
        const int k0 = ch * 64;
        #pragma unroll
        for (int i = 0; i < 2; i++) {
            int idx = tid + i * 256;                 // 0..511
            int r = idx >> 3, cb = (idx & 7) * 16;
            size_t tb = ((size_t)(b * SEQ + k0 + r) * QKVF + h * HDIM) * 2 + cb;
            uint32_t so = r * FA_ROWB + cb;
            CP_ASYNC16(stg + FA_KH + so, (const char*)qkh + tb + EMB * 2);
            CP_ASYNC16(stg + FA_KL + so, (const char*)qkl + tb + EMB * 2);
            CP_ASYNC16(stg + FA_VH + so, (const char*)qkh + tb + 2 * EMB * 2);
            CP_ASYNC16(stg + FA_VL + so, (const char*)qkl + tb + 2 * EMB * 2);
        }
        if (tid < 64) {
            float* md = (float*)(sm + FA_OFF_MADD) + (ch & 1) * 64;
            md[tid] = mask[b * SEQ + k0 + tid] ? 0.f : -1e9f;
        }
    };

    // prologue: Q tile (h,l) + KV chunk 0, one commit group
    #pragma unroll
    for (int i = 0; i < 8; i++) {
        int idx = tid + i * 256;                     // 0..2047
        int t2 = idx >> 10;                          // 0 = hi, 1 = lo
        int r  = (idx >> 3) & 127;
        int cb = (idx & 7) * 16;
        size_t gb = ((size_t)(tok0 + r) * QKVF + h * HDIM) * 2 + cb;
        const char* src = (const char*)(t2 ? qkl : qkh) + gb;
        CP_ASYNC16(smb + (t2 ? FA_OFF_QL : FA_OFF_QH) + r * FA_ROWB + cb, src);
    }
    load_kv(0);
    CP_COMMIT();

    // lane decompositions
    const int g  = lane >> 2, tq = lane & 3;
    const int a_row = lane & 15, a_k8 = (lane >> 4) * 8;
    const int bq = lane >> 3;
    const int b_r = (bq >> 1) * 8 + (lane & 7), b_k8 = (bq & 1) * 8;
    const int v_r = (bq & 1) * 8 + (lane & 7),  v_n8 = (bq >> 1) * 8;

    uint32_t qfh[4][4], qfl[4][4];
    float m0r = -1e30f, m1r = -1e30f, l0 = 0.f, l1 = 0.f;
    float o[8][4];
    #pragma unroll
    for (int j = 0; j < 8; j++)
        #pragma unroll
        for (int c = 0; c < 4; c++) o[j][c] = 0.f;

    const int NCH = SEQ / 64;
    for (int ch = 0; ch < NCH; ch++) {
        if (ch + 1 < NCH) { load_kv(ch + 1); CP_COMMIT(); CP_WAIT(1); }
        else              { CP_WAIT(0); }
        __syncthreads();
        const uint32_t stg = smb + FA_OFF_KV + (ch & 1) * FA_STAGE;

        if (ch == 0) {
            #pragma unroll
            for (int ks = 0; ks < 4; ks++) {
                uint32_t qoff = ((wid * 16 + a_row) * FA_LDS + ks * 16 + a_k8) * 2;
                LDMATRIX_X4(qfh[ks][0], qfh[ks][1], qfh[ks][2], qfh[ks][3],
                            smb + FA_OFF_QH + qoff);
                LDMATRIX_X4(qfl[ks][0], qfl[ks][1], qfl[ks][2], qfl[ks][3],
                            smb + FA_OFF_QL + qoff);
            }
        }

        // ---- S = Q K^T (16 x 64 per warp), 3-term bf16 ----
        float s[8][4];
        #pragma unroll
        for (int j = 0; j < 8; j++)
            #pragma unroll
            for (int c = 0; c < 4; c++) s[j][c] = 0.f;

        #pragma unroll
        for (int ks = 0; ks < 4; ks++) {
            uint32_t kh[8][2], kl[8][2];
            #pragma unroll
            for (int p = 0; p < 4; p++) {
                uint32_t boff = ((p * 16 + b_r) * FA_LDS + ks * 16 + b_k8) * 2;
                LDMATRIX_X4(kh[2*p][0], kh[2*p][1], kh[2*p+1][0], kh[2*p+1][1],
                            stg + FA_KH + boff);
                LDMATRIX_X4(kl[2*p][0], kl[2*p][1], kl[2*p+1][0], kl[2*p+1][1],
                            stg + FA_KL + boff);
            }
            #pragma unroll
            for (int j = 0; j < 8; j++) {
                MMA_BF16(s[j][0], s[j][1], s[j][2], s[j][3],
                         qfh[ks][0], qfh[ks][1], qfh[ks][2], qfh[ks][3],
                         kh[j][0], kh[j][1]);
                MMA_BF16(s[j][0], s[j][1], s[j][2], s[j][3],
                         qfh[ks][0], qfh[ks][1], qfh[ks][2], qfh[ks][3],
                         kl[j][0], kl[j][1]);
                MMA_BF16(s[j][0], s[j][1], s[j][2], s[j][3],
                         qfl[ks][0], qfl[ks][1], qfl[ks][2], qfl[ks][3],
                         kh[j][0], kh[j][1]);
            }
        }

        // ---- online softmax (exp2 domain, scores pre-scaled by C1) ----
        const float* md = (const float*)(sm + FA_OFF_MADD) + (ch & 1) * 64;
        #pragma unroll
        for (int j = 0; j < 8; j++) {
            float m0 = md[j * 8 + tq * 2];
            float m1 = md[j * 8 + tq * 2 + 1];
            s[j][0] = fmaf(s[j][0], FA_C1, m0);
            s[j][1] = fmaf(s[j][1], FA_C1, m1);
            s[j][2] = fmaf(s[j][2], FA_C1, m0);
            s[j][3] = fmaf(s[j][3], FA_C1, m1);
        }
        float rm0 = -1e30f, rm1 = -1e30f;
        #pragma unroll
        for (int j = 0; j < 8; j++) {
            rm0 = fmaxf(rm0, fmaxf(s[j][0], s[j][1]));
            rm1 = fmaxf(rm1, fmaxf(s[j][2], s[j][3]));
        }
        rm0 = fmaxf(rm0, __shfl_xor_sync(0xffffffffu, rm0, 1));
        rm0 = fmaxf(rm0, __shfl_xor_sync(0xffffffffu, rm0, 2));
        rm1 = fmaxf(rm1, __shfl_xor_sync(0xffffffffu, rm1, 1));
        rm1 = fmaxf(rm1, __shfl_xor_sync(0xffffffffu, rm1, 2));
        const float mn0 = fmaxf(m0r, rm0);
        const float mn1 = fmaxf(m1r, rm1);
        const float al0 = ex2f(m0r - mn0);
        const float al1 = ex2f(m1r - mn1);
        m0r = mn0; m1r = mn1;

        float rs0 = 0.f, rs1 = 0.f;
        #pragma unroll
        for (int j = 0; j < 8; j++) {
            s[j][0] = ex2f(s[j][0] - mn0);
            s[j][1] = ex2f(s[j][1] - mn0);
            s[j][2] = ex2f(s[j][2] - mn1);
            s[j][3] = ex2f(s[j][3] - mn1);
            rs0 += s[j][0] + s[j][1];
            rs1 += s[j][2] + s[j][3];
        }
        rs0 += __shfl_xor_sync(0xffffffffu, rs0, 1);
        rs0 += __shfl_xor_sync(0xffffffffu, rs0, 2);
        rs1 += __shfl_xor_sync(0xffffffffu, rs1, 1);
        rs1 += __shfl_xor_sync(0xffffffffu, rs1, 2);
        l0 = l0 * al0 + rs0;
        l1 = l1 * al1 + rs1;

        #pragma unroll
        for (int j = 0; j < 8; j++) {
            o[j][0] *= al0; o[j][1] *= al0;
            o[j][2] *= al1; o[j][3] *= al1;
        }

        // ---- pack P into A-fragments (hi + residual lo) ----
        uint32_t pah[4][4], pal[4][4];
        #pragma unroll
        for (int ks = 0; ks < 4; ks++) {
            const int j0 = 2 * ks, j1 = 2 * ks + 1;
            pah[ks][0] = pack_hi_lo(s[j0][0], s[j0][1], pal[ks][0]);
            pah[ks][1] = pack_hi_lo(s[j0][2], s[j0][3], pal[ks][1]);
            pah[ks][2] = pack_hi_lo(s[j1][0], s[j1][1], pal[ks][2]);
            pah[ks][3] = pack_hi_lo(s[j1][2], s[j1][3], pal[ks][3]);
        }

        // ---- O += P @ V (V via trans ldmatrix), 3-term ----
        #pragma unroll
        for (int ks = 0; ks < 4; ks++) {
            #pragma unroll
            for (int d = 0; d < 4; d++) {
                uint32_t vh[4], vl[4];
                uint32_t voff = ((ks * 16 + v_r) * FA_LDS + d * 16 + v_n8) * 2;
                LDMATRIX_X4_T(vh[0], vh[1], vh[2], vh[3], stg + FA_VH + voff);
                LDMATRIX_X4_T(vl[0], vl[1], vl[2], vl[3], stg + FA_VL + voff);
                MMA_BF16(o[2*d][0], o[2*d][1], o[2*d][2], o[2*d][3],
                         pah[ks][0], pah[ks][1], pah[ks][2], pah[ks][3], vh[0], vh[1]);
                MMA_BF16(o[2*d][0], o[2*d][1], o[2*d][2], o[2*d][3],
                         pah[ks][0], pah[ks][1], pah[ks][2], pah[ks][3], vl[0], vl[1]);
                MMA_BF16(o[2*d][0], o[2*d][1], o[2*d][2], o[2*d][3],
                         pal[ks][0], pal[ks][1], pal[ks][2], pal[ks][3], vh[0], vh[1]);
                MMA_BF16(o[2*d+1][0], o[2*d+1][1], o[2*d+1][2], o[2*d+1][3],
                         pah[ks][0], pah[ks][1], pah[ks][2], pah[ks][3], vh[2], vh[3]);
                MMA_BF16(o[2*d+1][0], o[2*d+1][1], o[2*d+1][2], o[2*d+1][3],
                         pah[ks][0], pah[ks][1], pah[ks][2], pah[ks][3], vl[2], vl[3]);
                MMA_BF16(o[2*d+1][0], o[2*d+1][1], o[2*d+1][2], o[2*d+1][3],
                         pal[ks][0], pal[ks][1], pal[ks][2], pal[ks][3], vh[2], vh[3]);
            }
        }
        __syncthreads();
    }

    // ---- epilogue: normalize, split hi/lo, write [token][h*64+dim] ----
    const float inv0 = 1.f / l0;
    const float inv1 = 1.f / l1;
    const int r0 = tok0 + wid * 16 + g;
    const int r1 = r0 + 8;
    #pragma unroll
    for (int j = 0; j < 8; j++) {
        const int col = h * HDIM + j * 8 + tq * 2;
        uint32_t lo0, lo1;
        uint32_t hi0 = pack_hi_lo(o[j][0] * inv0, o[j][1] * inv0, lo0);
        uint32_t hi1 = pack_hi_lo(o[j][2] * inv1, o[j][3] * inv1, lo1);
        *(uint32_t*)(oh + (size_t)r0 * EMB + col) = hi0;
        *(uint32_t*)(ol + (size_t)r0 * EMB + col) = lo0;
        *(uint32_t*)(oh + (size_t)r1 * EMB + col) = hi1;
        *(uint32_t*)(ol + (size_t)r1 * EMB + col) = lo1;
    }
}

// ---------------------------------------------------------------------------
extern "C" void kernel_launch(void* const* d_in, const int* in_sizes, int n_in,
                              void* d_out, int out_size)
{
    const float* x     = (const float*)d_in[0];
    const float* w_qkv = (const float*)d_in[1];
    const float* w_out = (const float*)d_in[2];
    const float* b_out = (const float*)d_in[3];
    const int*   mask  = (const int*)  d_in[4];
    float* out = (float*)d_out;

    __nv_bfloat16 *xh, *xl, *wqh, *wql, *woh, *wol, *qkh, *qkl, *ath, *atl;
    cudaGetSymbolAddress((void**)&xh,  g_xh);
    cudaGetSymbolAddress((void**)&xl,  g_xl);
    cudaGetSymbolAddress((void**)&wqh, g_wqkvh);
    cudaGetSymbolAddress((void**)&wql, g_wqkvl);
    cudaGetSymbolAddress((void**)&woh, g_wouth);
    cudaGetSymbolAddress((void**)&wol, g_woutl);
    cudaGetSymbolAddress((void**)&qkh, g_qkvh);
    cudaGetSymbolAddress((void**)&qkl, g_qkvl);
    cudaGetSymbolAddress((void**)&ath, g_atth);
    cudaGetSymbolAddress((void**)&atl, g_attl);

    cudaFuncSetAttribute((const void*)gemm_mma_kernel<false, true>,
                         cudaFuncAttributeMaxDynamicSharedMemorySize, GM_SMEM);
    cudaFuncSetAttribute((const void*)gemm_mma_kernel<true, false>,
                         cudaFuncAttributeMaxDynamicSharedMemorySize, GM_SMEM);
    cudaFuncSetAttribute((const void*)flash_mma_kernel,
                         cudaFuncAttributeMaxDynamicSharedMemorySize, FA_SMEM);

    // 0) splits
    {
        int n4 = TOK * EMB / 4;
        split_kernel<<<(n4 + 255) / 256, 256>>>((const float4*)x, xh, xl, n4);
        n4 = QKVF * EMB / 4;
        split_kernel<<<(n4 + 255) / 256, 256>>>((const float4*)w_qkv, wqh, wql, n4);
        n4 = EMB * EMB / 4;
        split_kernel<<<(n4 + 255) / 256, 256>>>((const float4*)w_out, woh, wol, n4);
    }

    // 1) QKV projection -> bf16 hi/lo qkv directly
    {
        dim3 grid(QKVF / BN, TOK / BM);
        gemm_mma_kernel<false, true><<<grid, 256, GM_SMEM>>>(
            xh, xl, wqh, wql, nullptr, nullptr, qkh, qkl, TOK, QKVF, EMB);
    }

    // 2) Flash attention (tensor cores) -> bf16 hi/lo attn
    {
        dim3 grid(SEQ / 128, HEADS, BATCH);
        flash_mma_kernel<<<grid, 256, FA_SMEM>>>(qkh, qkl, mask, ath, atl);
    }

    // 3) Output projection + bias -> f32 out
    {
        dim3 grid(EMB / BN, TOK / BM);
        gemm_mma_kernel<true, false><<<grid, 256, GM_SMEM>>>(
            ath, atl, woh, wol, b_out, out, nullptr, nullptr, TOK, EMB, EMB);
    }
}

// round 5
// speedup vs baseline: 4.2804x; 1.1584x over previous
#include <cuda_runtime.h>
#include <cuda_bf16.h>
#include <math.h>
#include <stdint.h>

// Problem constants
#define BATCH 4
#define SEQ   2048
#define EMB   1024
#define HEADS 16
#define HDIM  64
#define TOK   (BATCH * SEQ)          // 8192
#define QKVF  (3 * EMB)              // 3072

// Scratch (device globals — no allocation allowed)
__device__ __nv_bfloat16 g_xh[(size_t)TOK * EMB];
__device__ __nv_bfloat16 g_xl[(size_t)TOK * EMB];
__device__ __nv_bfloat16 g_wqkvh[(size_t)QKVF * EMB];
__device__ __nv_bfloat16 g_wqkvl[(size_t)QKVF * EMB];
__device__ __nv_bfloat16 g_wouth[(size_t)EMB * EMB];
__device__ __nv_bfloat16 g_woutl[(size_t)EMB * EMB];
__device__ __nv_bfloat16 g_qkvh[(size_t)TOK * QKVF];
__device__ __nv_bfloat16 g_qkvl[(size_t)TOK * QKVF];
__device__ __nv_bfloat16 g_atth[(size_t)TOK * EMB];
__device__ __nv_bfloat16 g_attl[(size_t)TOK * EMB];

// ---------------------------------------------------------------------------
// PTX helpers — only sm_80+ features (compute_103 baseline safe)
// ---------------------------------------------------------------------------
__device__ __forceinline__ uint32_t smem_u32(const void* p) {
    uint32_t a;
    asm("{ .reg .u64 t; cvta.to.shared.u64 t, %1; cvt.u32.u64 %0, t; }"
        : "=r"(a) : "l"(p));
    return a;
}

#define CP_ASYNC16(dst, src) \
    asm volatile("cp.async.cg.shared.global [%0], [%1], 16;" :: "r"(dst), "l"(src))
#define CP_COMMIT() asm volatile("cp.async.commit_group;")
#define CP_WAIT(n)  asm volatile("cp.async.wait_group %0;" :: "n"(n))

#define LDMATRIX_X4(r0, r1, r2, r3, addr) \
    asm volatile("ldmatrix.sync.aligned.m8n8.x4.shared.b16 {%0,%1,%2,%3}, [%4];" \
                 : "=r"(r0), "=r"(r1), "=r"(r2), "=r"(r3) : "r"(addr))
#define LDMATRIX_X4_T(r0, r1, r2, r3, addr) \
    asm volatile("ldmatrix.sync.aligned.m8n8.x4.trans.shared.b16 {%0,%1,%2,%3}, [%4];" \
                 : "=r"(r0), "=r"(r1), "=r"(r2), "=r"(r3) : "r"(addr))

#define MMA_BF16(c0, c1, c2, c3, a0, a1, a2, a3, b0, b1) \
    asm volatile("mma.sync.aligned.m16n8k16.row.col.f32.bf16.bf16.f32 " \
                 "{%0,%1,%2,%3}, {%4,%5,%6,%7}, {%8,%9}, {%0,%1,%2,%3};" \
                 : "+f"(c0), "+f"(c1), "+f"(c2), "+f"(c3) \
                 : "r"(a0), "r"(a1), "r"(a2), "r"(a3), "r"(b0), "r"(b1))

__device__ __forceinline__ float ex2f(float x) {
    float y;
    asm("ex2.approx.f32 %0, %1;" : "=f"(y) : "f"(x));
    return y;
}

__device__ __forceinline__ uint32_t pack_hi_lo(float a, float b, uint32_t& lo) {
    __nv_bfloat162 h = __floats2bfloat162_rn(a, b);
    float ra = a - __bfloat162float(h.x);
    float rb = b - __bfloat162float(h.y);
    __nv_bfloat162 r = __floats2bfloat162_rn(ra, rb);
    lo = reinterpret_cast<uint32_t&>(r);
    return reinterpret_cast<uint32_t&>(h);
}

// SW128 XOR swizzle on byte offsets (rows of 128B): conflict-free ldmatrix
#define SW128(off) ((uint32_t)(off) ^ ((((uint32_t)(off)) >> 3) & 0x70))

// ---------------------------------------------------------------------------
// fp32 -> bf16 hi/lo split
// ---------------------------------------------------------------------------
__global__ void __launch_bounds__(256) split_kernel(
    const float4* __restrict__ in, __nv_bfloat16* __restrict__ hi,
    __nv_bfloat16* __restrict__ lo, int n4)
{
    int i = blockIdx.x * blockDim.x + threadIdx.x;
    if (i >= n4) return;
    float4 v = in[i];
    float f[4] = {v.x, v.y, v.z, v.w};
    __nv_bfloat16 h[4], l[4];
    #pragma unroll
    for (int j = 0; j < 4; j++) {
        h[j] = __float2bfloat16(f[j]);
        l[j] = __float2bfloat16(f[j] - __bfloat162float(h[j]));
    }
    ((uint2*)hi)[i] = *(uint2*)h;
    ((uint2*)lo)[i] = *(uint2*)l;
}

// ---------------------------------------------------------------------------
// mma.sync GEMM:  C[M,N] = A[M,K] * B[N,K]^T (+ bias[N])
// bf16 hi/lo 3-term, fp32 accum. CTA 128x128, BK=32, 8 warps (2x4).
// SW128-swizzled smem rows: [32 hi bf16 | 32 lo bf16] = 128B.
// 3-stage cp.async pipeline; term-reordered MMAs break RAW chains.
// ---------------------------------------------------------------------------
#define BM 128
#define BN 128
#define BK 32
#define TILE_B (128 * 128)          // 16 KB: combined hi|lo tile
#define STAGE_B (2 * TILE_B)        // A + B = 32 KB
#define OFF_A 0
#define OFF_B TILE_B
#define GM_SMEM (3 * STAGE_B)       // 98304

template <bool BIAS, bool SPLIT>
__global__ void __launch_bounds__(256, 2) gemm_mma_kernel(
    const __nv_bfloat16* __restrict__ Ah, const __nv_bfloat16* __restrict__ Al,
    const __nv_bfloat16* __restrict__ Bh, const __nv_bfloat16* __restrict__ Bl,
    const float* __restrict__ bias, float* __restrict__ C,
    __nv_bfloat16* __restrict__ Ch, __nv_bfloat16* __restrict__ Cl,
    int M, int N, int K)
{
    extern __shared__ char sm[];
    const uint32_t smb = smem_u32(sm);
    const int tid  = threadIdx.x;
    const int wid  = tid >> 5;
    const int lane = tid & 31;
    const int m0 = blockIdx.y * BM;
    const int n0 = blockIdx.x * BN;
    const int warp_m = (wid >> 2) * 64;
    const int warp_n = (wid & 3) * 32;

    const char* Ahc = (const char*)Ah;
    const char* Alc = (const char*)Al;
    const char* Bhc = (const char*)Bh;
    const char* Blc = (const char*)Bl;

    auto load_chunk = [&](int k0, int stg) {
        const uint32_t sb = smb + stg * STAGE_B;
        #pragma unroll
        for (int i = 0; i < 4; i++) {
            int idx = tid + i * 256;           // 0..1023
            int r = idx >> 3;                  // 0..127
            int c = (idx & 7) * 16;            // 0..112
            uint32_t so = SW128(r * 128 + c);
            size_t gA = ((size_t)(m0 + r) * K + k0) * 2;
            size_t gB = ((size_t)(n0 + r) * K + k0) * 2;
            const char* sA = (c < 64) ? (Ahc + gA + c) : (Alc + gA + c - 64);
            const char* sB = (c < 64) ? (Bhc + gB + c) : (Blc + gB + c - 64);
            CP_ASYNC16(sb + OFF_A + so, sA);
            CP_ASYNC16(sb + OFF_B + so, sB);
        }
    };

    float acc[4][4][4];
    #pragma unroll
    for (int i = 0; i < 4; i++)
        #pragma unroll
        for (int j = 0; j < 4; j++)
            #pragma unroll
            for (int c = 0; c < 4; c++) acc[i][j][c] = 0.f;

    const int nch = K / BK;
    load_chunk(0, 0); CP_COMMIT();
    load_chunk(BK, 1); CP_COMMIT();

    // lane addressing (byte columns)
    const int a_row  = lane & 15;
    const int a_kofb = (lane >> 4) * 16;
    const int bq     = lane >> 3;
    const int b_row  = (bq >> 1) * 8 + (lane & 7);
    const int b_kofb = (bq & 1) * 16;

    int stg = 0;
    for (int ch = 0; ch < nch; ch++) {
        CP_WAIT(1);
        __syncthreads();
        if (ch + 2 < nch) {
            int s2 = stg + 2; if (s2 >= 3) s2 -= 3;
            load_chunk((ch + 2) * BK, s2);
        }
        CP_COMMIT();

        const uint32_t sb = smb + stg * STAGE_B;
        #pragma unroll
        for (int ks = 0; ks < 2; ks++) {
            const int kb = ks * 32;            // byte col of k-step
            uint32_t bh[4][2], bl[4][2];
            #pragma unroll
            for (int p = 0; p < 2; p++) {
                uint32_t row = (warp_n + p * 16 + b_row) * 128;
                LDMATRIX_X4(bh[2*p][0], bh[2*p][1], bh[2*p+1][0], bh[2*p+1][1],
                            sb + OFF_B + SW128(row + kb + b_kofb));
                LDMATRIX_X4(bl[2*p][0], bl[2*p][1], bl[2*p+1][0], bl[2*p+1][1],
                            sb + OFF_B + SW128(row + 64 + kb + b_kofb));
            }
            #pragma unroll
            for (int mi = 0; mi < 4; mi++) {
                uint32_t ah[4], al[4];
                uint32_t row = (warp_m + mi * 16 + a_row) * 128;
                LDMATRIX_X4(ah[0], ah[1], ah[2], ah[3],
                            sb + OFF_A + SW128(row + kb + a_kofb));
                LDMATRIX_X4(al[0], al[1], al[2], al[3],
                            sb + OFF_A + SW128(row + 64 + kb + a_kofb));
                // term-reordered: 4 independent MMAs between same-acc deps
                #pragma unroll
                for (int nj = 0; nj < 4; nj++)
                    MMA_BF16(acc[mi][nj][0], acc[mi][nj][1], acc[mi][nj][2], acc[mi][nj][3],
                             ah[0], ah[1], ah[2], ah[3], bh[nj][0], bh[nj][1]);
                #pragma unroll
                for (int nj = 0; nj < 4; nj++)
                    MMA_BF16(acc[mi][nj][0], acc[mi][nj][1], acc[mi][nj][2], acc[mi][nj][3],
                             ah[0], ah[1], ah[2], ah[3], bl[nj][0], bl[nj][1]);
                #pragma unroll
                for (int nj = 0; nj < 4; nj++)
                    MMA_BF16(acc[mi][nj][0], acc[mi][nj][1], acc[mi][nj][2], acc[mi][nj][3],
                             al[0], al[1], al[2], al[3], bh[nj][0], bh[nj][1]);
            }
        }
        if (++stg == 3) stg = 0;
    }

    const int g = lane >> 2, t = lane & 3;
    #pragma unroll
    for (int mi = 0; mi < 4; mi++) {
        const int row = m0 + warp_m + mi * 16 + g;
        #pragma unroll
        for (int nj = 0; nj < 4; nj++) {
            const int col = n0 + warp_n + nj * 8 + t * 2;
            if (SPLIT) {
                uint32_t lo0, lo1;
                uint32_t hi0 = pack_hi_lo(acc[mi][nj][0], acc[mi][nj][1], lo0);
                uint32_t hi1 = pack_hi_lo(acc[mi][nj][2], acc[mi][nj][3], lo1);
                *(uint32_t*)(Ch + (size_t)row * N + col)       = hi0;
                *(uint32_t*)(Cl + (size_t)row * N + col)       = lo0;
                *(uint32_t*)(Ch + (size_t)(row + 8) * N + col) = hi1;
                *(uint32_t*)(Cl + (size_t)(row + 8) * N + col) = lo1;
            } else {
                float b0 = 0.f, b1 = 0.f;
                if (BIAS) { b0 = bias[col]; b1 = bias[col + 1]; }
                float2 v0 = {acc[mi][nj][0] + b0, acc[mi][nj][1] + b1};
                float2 v1 = {acc[mi][nj][2] + b0, acc[mi][nj][3] + b1};
                *(float2*)(C + (size_t)row * N + col)       = v0;
                *(float2*)(C + (size_t)(row + 8) * N + col) = v1;
            }
        }
    }
}

// ---------------------------------------------------------------------------
// Flash attention with mma.sync (bf16 hi/lo 3-term, fp32 softmax/accum)
// grid (SEQ/128, HEADS, BATCH), 256 threads. SW128-swizzled smem, 2 CTAs/SM.
// Q fragments re-loaded from smem each chunk (register relief).
// ---------------------------------------------------------------------------
#define FA_OFF_QH 0
#define FA_OFF_QL 16384
#define FA_OFF_KV 32768
#define FA_KH 0
#define FA_KL 8192
#define FA_VH 16384
#define FA_VL 24576
#define FA_STAGE 32768
#define FA_OFF_MADD (FA_OFF_KV + 2 * FA_STAGE)   // 98304
#define FA_SMEM (FA_OFF_MADD + 2 * 64 * 4)       // 98816
#define FA_C1 0.18033688011112042f               // 0.125 * log2(e)

__global__ void __launch_bounds__(256, 2) flash_mma_kernel(
    const __nv_bfloat16* __restrict__ qkh, const __nv_bfloat16* __restrict__ qkl,
    const int* __restrict__ mask,
    __nv_bfloat16* __restrict__ oh, __nv_bfloat16* __restrict__ ol)
{
    extern __shared__ char sm[];
    const uint32_t smb = smem_u32(sm);
    const int tid = threadIdx.x, wid = tid >> 5, lane = tid & 31;
    const int qb = blockIdx.x, h = blockIdx.y, b = blockIdx.z;
    const int tok0 = b * SEQ + qb * 128;

    const char* qkhc = (const char*)qkh;
    const char* qklc = (const char*)qkl;

    auto load_kv = [&](int ch) {
        const uint32_t stg = smb + FA_OFF_KV + (ch & 1) * FA_STAGE;
        const int k0 = ch * 64;
        #pragma unroll
        for (int i = 0; i < 8; i++) {
            int idx = tid + i * 256;                 // 0..2047
            int tile = idx >> 9;                     // 0..3: KH,KL,VH,VL
            int r = (idx >> 3) & 63;
            int c = (idx & 7) * 16;
            size_t gK = ((size_t)(b * SEQ + k0 + r) * QKVF + EMB + h * HDIM) * 2 + c;
            size_t gV = gK + (size_t)EMB * 2;
            const char* src;
            if      (tile == 0) src = qkhc + gK;
            else if (tile == 1) src = qklc + gK;
            else if (tile == 2) src = qkhc + gV;
            else                src = qklc + gV;
            CP_ASYNC16(stg + tile * 8192 + SW128(r * 128 + c), src);
        }
        if (tid < 64) {
            float* md = (float*)(sm + FA_OFF_MADD) + (ch & 1) * 64;
            md[tid] = mask[b * SEQ + k0 + tid] ? 0.f : -1e9f;
        }
    };

    // prologue: Q tiles + KV chunk 0 in one commit group
    #pragma unroll
    for (int i = 0; i < 8; i++) {
        int idx = tid + i * 256;                     // 0..2047
        int t2 = idx >> 10;                          // 0 = hi, 1 = lo
        int r  = (idx >> 3) & 127;
        int c  = (idx & 7) * 16;
        size_t gb = ((size_t)(tok0 + r) * QKVF + h * HDIM) * 2 + c;
        const char* src = (t2 ? qklc : qkhc) + gb;
        CP_ASYNC16(smb + (t2 ? FA_OFF_QL : FA_OFF_QH) + SW128(r * 128 + c), src);
    }
    load_kv(0);
    CP_COMMIT();

    const int g  = lane >> 2, tq = lane & 3;
    const int a_row = lane & 15, a_kb = (lane >> 4) * 16;
    const int bq = lane >> 3;
    const int b_r = (bq >> 1) * 8 + (lane & 7), b_kb = (bq & 1) * 16;
    const int v_r = (bq & 1) * 8 + (lane & 7),  v_nb = (bq >> 1) * 16;

    float m0r = -1e30f, m1r = -1e30f, l0 = 0.f, l1 = 0.f;
    float o[8][4];
    #pragma unroll
    for (int j = 0; j < 8; j++)
        #pragma unroll
        for (int c = 0; c < 4; c++) o[j][c] = 0.f;

    const int NCH = SEQ / 64;
    for (int ch = 0; ch < NCH; ch++) {
        if (ch + 1 < NCH) { load_kv(ch + 1); CP_COMMIT(); CP_WAIT(1); }
        else              { CP_WAIT(0); }
        __syncthreads();
        const uint32_t stg = smb + FA_OFF_KV + (ch & 1) * FA_STAGE;

        // ---- S = Q K^T (16 x 64 per warp), 3-term bf16, term-reordered ----
        float s[8][4];
        #pragma unroll
        for (int j = 0; j < 8; j++)
            #pragma unroll
            for (int c = 0; c < 4; c++) s[j][c] = 0.f;

        #pragma unroll
        for (int ks = 0; ks < 4; ks++) {
            const int kb = ks * 32;
            uint32_t qh[4], ql[4];
            uint32_t qrow = (wid * 16 + a_row) * 128;
            LDMATRIX_X4(qh[0], qh[1], qh[2], qh[3],
                        smb + FA_OFF_QH + SW128(qrow + kb + a_kb));
            LDMATRIX_X4(ql[0], ql[1], ql[2], ql[3],
                        smb + FA_OFF_QL + SW128(qrow + kb + a_kb));
            uint32_t kh[8][2], kl[8][2];
            #pragma unroll
            for (int p = 0; p < 4; p++) {
                uint32_t krow = (p * 16 + b_r) * 128;
                LDMATRIX_X4(kh[2*p][0], kh[2*p][1], kh[2*p+1][0], kh[2*p+1][1],
                            stg + FA_KH + SW128(krow + kb + b_kb));
                LDMATRIX_X4(kl[2*p][0], kl[2*p][1], kl[2*p+1][0], kl[2*p+1][1],
                            stg + FA_KL + SW128(krow + kb + b_kb));
            }
            #pragma unroll
            for (int j = 0; j < 8; j++)
                MMA_BF16(s[j][0], s[j][1], s[j][2], s[j][3],
                         qh[0], qh[1], qh[2], qh[3], kh[j][0], kh[j][1]);
            #pragma unroll
            for (int j = 0; j < 8; j++)
                MMA_BF16(s[j][0], s[j][1], s[j][2], s[j][3],
                         qh[0], qh[1], qh[2], qh[3], kl[j][0], kl[j][1]);
            #pragma unroll
            for (int j = 0; j < 8; j++)
                MMA_BF16(s[j][0], s[j][1], s[j][2], s[j][3],
                         ql[0], ql[1], ql[2], ql[3], kh[j][0], kh[j][1]);
        }

        // ---- online softmax (exp2 domain) ----
        const float* md = (const float*)(sm + FA_OFF_MADD) + (ch & 1) * 64;
        #pragma unroll
        for (int j = 0; j < 8; j++) {
            float m0 = md[j * 8 + tq * 2];
            float m1 = md[j * 8 + tq * 2 + 1];
            s[j][0] = fmaf(s[j][0], FA_C1, m0);
            s[j][1] = fmaf(s[j][1], FA_C1, m1);
            s[j][2] = fmaf(s[j][2], FA_C1, m0);
            s[j][3] = fmaf(s[j][3], FA_C1, m1);
        }
        float rm0 = -1e30f, rm1 = -1e30f;
        #pragma unroll
        for (int j = 0; j < 8; j++) {
            rm0 = fmaxf(rm0, fmaxf(s[j][0], s[j][1]));
            rm1 = fmaxf(rm1, fmaxf(s[j][2], s[j][3]));
        }
        rm0 = fmaxf(rm0, __shfl_xor_sync(0xffffffffu, rm0, 1));
        rm0 = fmaxf(rm0, __shfl_xor_sync(0xffffffffu, rm0, 2));
        rm1 = fmaxf(rm1, __shfl_xor_sync(0xffffffffu, rm1, 1));
        rm1 = fmaxf(rm1, __shfl_xor_sync(0xffffffffu, rm1, 2));
        const float mn0 = fmaxf(m0r, rm0);
        const float mn1 = fmaxf(m1r, rm1);
        const float al0 = ex2f(m0r - mn0);
        const float al1 = ex2f(m1r - mn1);
        m0r = mn0; m1r = mn1;

        float rs0 = 0.f, rs1 = 0.f;
        #pragma unroll
        for (int j = 0; j < 8; j++) {
            s[j][0] = ex2f(s[j][0] - mn0);
            s[j][1] = ex2f(s[j][1] - mn0);
            s[j][2] = ex2f(s[j][2] - mn1);
            s[j][3] = ex2f(s[j][3] - mn1);
            rs0 += s[j][0] + s[j][1];
            rs1 += s[j][2] + s[j][3];
        }
        rs0 += __shfl_xor_sync(0xffffffffu, rs0, 1);
        rs0 += __shfl_xor_sync(0xffffffffu, rs0, 2);
        rs1 += __shfl_xor_sync(0xffffffffu, rs1, 1);
        rs1 += __shfl_xor_sync(0xffffffffu, rs1, 2);
        l0 = l0 * al0 + rs0;
        l1 = l1 * al1 + rs1;

        #pragma unroll
        for (int j = 0; j < 8; j++) {
            o[j][0] *= al0; o[j][1] *= al0;
            o[j][2] *= al1; o[j][3] *= al1;
        }

        // ---- pack P into A-fragments ----
        uint32_t pah[4][4], pal[4][4];
        #pragma unroll
        for (int ks = 0; ks < 4; ks++) {
            const int j0 = 2 * ks, j1 = 2 * ks + 1;
            pah[ks][0] = pack_hi_lo(s[j0][0], s[j0][1], pal[ks][0]);
            pah[ks][1] = pack_hi_lo(s[j0][2], s[j0][3], pal[ks][1]);
            pah[ks][2] = pack_hi_lo(s[j1][0], s[j1][1], pal[ks][2]);
            pah[ks][3] = pack_hi_lo(s[j1][2], s[j1][3], pal[ks][3]);
        }

        // ---- O += P @ V, 3-term, term-reordered ----
        #pragma unroll
        for (int ks = 0; ks < 4; ks++) {
            uint32_t vh[4][4], vl[4][4];
            #pragma unroll
            for (int d = 0; d < 4; d++) {
                uint32_t voff = SW128((ks * 16 + v_r) * 128 + d * 32 + v_nb);
                LDMATRIX_X4_T(vh[d][0], vh[d][1], vh[d][2], vh[d][3], stg + FA_VH + voff);
                LDMATRIX_X4_T(vl[d][0], vl[d][1], vl[d][2], vl[d][3], stg + FA_VL + voff);
            }
            #pragma unroll
            for (int d = 0; d < 4; d++) {
                MMA_BF16(o[2*d][0], o[2*d][1], o[2*d][2], o[2*d][3],
                         pah[ks][0], pah[ks][1], pah[ks][2], pah[ks][3], vh[d][0], vh[d][1]);
                MMA_BF16(o[2*d+1][0], o[2*d+1][1], o[2*d+1][2], o[2*d+1][3],
                         pah[ks][0], pah[ks][1], pah[ks][2], pah[ks][3], vh[d][2], vh[d][3]);
            }
            #pragma unroll
            for (int d = 0; d < 4; d++) {
                MMA_BF16(o[2*d][0], o[2*d][1], o[2*d][2], o[2*d][3],
                         pah[ks][0], pah[ks][1], pah[ks][2], pah[ks][3], vl[d][0], vl[d][1]);
                MMA_BF16(o[2*d+1][0], o[2*d+1][1], o[2*d+1][2], o[2*d+1][3],
                         pah[ks][0], pah[ks][1], pah[ks][2], pah[ks][3], vl[d][2], vl[d][3]);
            }
            #pragma unroll
            for (int d = 0; d < 4; d++) {
                MMA_BF16(o[2*d][0], o[2*d][1], o[2*d][2], o[2*d][3],
                         pal[ks][0], pal[ks][1], pal[ks][2], pal[ks][3], vh[d][0], vh[d][1]);
                MMA_BF16(o[2*d+1][0], o[2*d+1][1], o[2*d+1][2], o[2*d+1][3],
                         pal[ks][0], pal[ks][1], pal[ks][2], pal[ks][3], vh[d][2], vh[d][3]);
            }
        }
        __syncthreads();
    }

    // ---- epilogue ----
    const float inv0 = 1.f / l0;
    const float inv1 = 1.f / l1;
    const int r0 = tok0 + wid * 16 + g;
    const int r1 = r0 + 8;
    #pragma unroll
    for (int j = 0; j < 8; j++) {
        const int col = h * HDIM + j * 8 + tq * 2;
        uint32_t lo0, lo1;
        uint32_t hi0 = pack_hi_lo(o[j][0] * inv0, o[j][1] * inv0, lo0);
        uint32_t hi1 = pack_hi_lo(o[j][2] * inv1, o[j][3] * inv1, lo1);
        *(uint32_t*)(oh + (size_t)r0 * EMB + col) = hi0;
        *(uint32_t*)(ol + (size_t)r0 * EMB + col) = lo0;
        *(uint32_t*)(oh + (size_t)r1 * EMB + col) = hi1;
        *(uint32_t*)(ol + (size_t)r1 * EMB + col) = lo1;
    }
}

// ---------------------------------------------------------------------------
extern "C" void kernel_launch(void* const* d_in, const int* in_sizes, int n_in,
                              void* d_out, int out_size)
{
    const float* x     = (const float*)d_in[0];
    const float* w_qkv = (const float*)d_in[1];
    const float* w_out = (const float*)d_in[2];
    const float* b_out = (const float*)d_in[3];
    const int*   mask  = (const int*)  d_in[4];
    float* out = (float*)d_out;

    __nv_bfloat16 *xh, *xl, *wqh, *wql, *woh, *wol, *qkh, *qkl, *ath, *atl;
    cudaGetSymbolAddress((void**)&xh,  g_xh);
    cudaGetSymbolAddress((void**)&xl,  g_xl);
    cudaGetSymbolAddress((void**)&wqh, g_wqkvh);
    cudaGetSymbolAddress((void**)&wql, g_wqkvl);
    cudaGetSymbolAddress((void**)&woh, g_wouth);
    cudaGetSymbolAddress((void**)&wol, g_woutl);
    cudaGetSymbolAddress((void**)&qkh, g_qkvh);
    cudaGetSymbolAddress((void**)&qkl, g_qkvl);
    cudaGetSymbolAddress((void**)&ath, g_atth);
    cudaGetSymbolAddress((void**)&atl, g_attl);

    cudaFuncSetAttribute((const void*)gemm_mma_kernel<false, true>,
                         cudaFuncAttributeMaxDynamicSharedMemorySize, GM_SMEM);
    cudaFuncSetAttribute((const void*)gemm_mma_kernel<true, false>,
                         cudaFuncAttributeMaxDynamicSharedMemorySize, GM_SMEM);
    cudaFuncSetAttribute((const void*)flash_mma_kernel,
                         cudaFuncAttributeMaxDynamicSharedMemorySize, FA_SMEM);

    // 0) splits
    {
        int n4 = TOK * EMB / 4;
        split_kernel<<<(n4 + 255) / 256, 256>>>((const float4*)x, xh, xl, n4);
        n4 = QKVF * EMB / 4;
        split_kernel<<<(n4 + 255) / 256, 256>>>((const float4*)w_qkv, wqh, wql, n4);
        n4 = EMB * EMB / 4;
        split_kernel<<<(n4 + 255) / 256, 256>>>((const float4*)w_out, woh, wol, n4);
    }

    // 1) QKV projection -> bf16 hi/lo qkv
    {
        dim3 grid(QKVF / BN, TOK / BM);
        gemm_mma_kernel<false, true><<<grid, 256, GM_SMEM>>>(
            xh, xl, wqh, wql, nullptr, nullptr, qkh, qkl, TOK, QKVF, EMB);
    }

    // 2) Flash attention -> bf16 hi/lo attn
    {
        dim3 grid(SEQ / 128, HEADS, BATCH);
        flash_mma_kernel<<<grid, 256, FA_SMEM>>>(qkh, qkl, mask, ath, atl);
    }

    // 3) Output projection + bias -> f32 out
    {
        dim3 grid(EMB / BN, TOK / BM);
        gemm_mma_kernel<true, false><<<grid, 256, GM_SMEM>>>(
            ath, atl, woh, wol, b_out, out, nullptr, nullptr, TOK, EMB, EMB);
    }
}